// round 2
// baseline (speedup 1.0000x reference)
#include <cuda_runtime.h>

#define BB 64
#define PP 256
#define NN 1000
#define EE 128
#define HH 8
#define DD 16
#define HD 128
#define PT 16   // queries per attention block
#define CC 32   // n-chunk

// scratch (allowed: __device__ globals, no allocation)
__device__ float g_K[BB * NN * HD];   // 32.8 MB
__device__ float g_V[BB * NN * HD];   // 32.8 MB
__device__ float g_Q[BB * PP * HD];   //  8.4 MB

// ---------------------------------------------------------------------------
// Kernel A: K/V projection.  rows = B*N = 64000, 8 rows/block, 256 threads.
// threads 0..127 -> K (Wk), 128..255 -> V (Wv). W cached in L1, 8-row reuse.
// ---------------------------------------------------------------------------
__global__ void kv_proj(const float* __restrict__ enc,
                        const float* __restrict__ Wk,
                        const float* __restrict__ Wv) {
    __shared__ float xs[8 * 128];
    int row0 = blockIdx.x * 8;
    int t = threadIdx.x;
    const float* src = enc + (size_t)row0 * 128;
    for (int i = t; i < 1024; i += 256) xs[i] = src[i];
    __syncthreads();

    int col = t & 127;
    const float* W = (t < 128) ? Wk : Wv;
    float* out = (t < 128) ? g_K : g_V;
    float acc[8] = {0, 0, 0, 0, 0, 0, 0, 0};
#pragma unroll 4
    for (int in = 0; in < 128; in++) {
        float w = W[in * 128 + col];
#pragma unroll
        for (int r = 0; r < 8; r++) acc[r] += xs[r * 128 + in] * w;
    }
#pragma unroll
    for (int r = 0; r < 8; r++) out[(size_t)(row0 + r) * 128 + col] = acc[r];
}

// ---------------------------------------------------------------------------
// Kernel B: Q projection (concat(last, attr) @ Wq).  rows = B*P = 16384,
// 8 rows/block, 128 threads, K=129.
// ---------------------------------------------------------------------------
__global__ void q_proj(const float* __restrict__ last,
                       const float* __restrict__ attr,
                       const float* __restrict__ Wq) {
    __shared__ float xs[8 * 132];
    int row0 = blockIdx.x * 8;
    int t = threadIdx.x;  // 128
    for (int i = t; i < 1024; i += 128) {
        int r = i >> 7, c = i & 127;
        xs[r * 132 + c] = last[(size_t)(row0 + r) * 128 + c];
    }
    if (t < 8) xs[t * 132 + 128] = attr[row0 + t];
    __syncthreads();

    float acc[8] = {0, 0, 0, 0, 0, 0, 0, 0};
#pragma unroll 4
    for (int in = 0; in < 129; in++) {
        float w = Wq[in * 128 + t];
#pragma unroll
        for (int r = 0; r < 8; r++) acc[r] += xs[r * 132 + in] * w;
    }
#pragma unroll
    for (int r = 0; r < 8; r++) g_Q[(size_t)(row0 + r) * 128 + t] = acc[r];
}

// ---------------------------------------------------------------------------
// Kernel C: fused attention + Wo + tanh-clipped scoring + final softmax.
// block = (b, 16-query tile). 256 threads, 1024 blocks.
// Online (flash) softmax over n-chunks of 32.
// Thread pairing: pi = t>>1 owns (head h = pi>>4, p = pi&15); the pair splits
// the D=16 accumulator 8/8 (d0 = (t&1)*8). Even thread does softmax bookkeeping.
// ---------------------------------------------------------------------------
__global__ void attn_kernel(const float* __restrict__ enc,
                            const float* __restrict__ mask,
                            const float* __restrict__ Wo,
                            const float* __restrict__ bo,
                            float* __restrict__ probs) {
    extern __shared__ float sm[];
    // layout (floats):
    //   [0, 2048)        mh_s (phase B)
    //   [2048, 6208)     ke_s : K chunk (stride 128) / enc chunk (stride 129)
    //   [6208, 22208)    big:
    //      phase A: v_s 4096 | s_s 4224 (stride 33) | mask_s 512 | resc 128 |
    //               l_s 128 | out_s 2048
    //      phase B: sc[16*1000]
    float* mh_s  = sm;
    float* ke_s  = sm + 2048;
    float* big   = sm + 6208;
    float* v_s    = big;
    float* s_s    = big + 4096;
    float* mask_s = big + 8320;
    float* resc   = big + 8832;
    float* l_s    = big + 8960;
    float* out_s  = big + 9088;
    float* sc     = big;

    int t = threadIdx.x;
    int b = blockIdx.x >> 4;
    int p0 = (blockIdx.x & 15) * PT;

    int pi = t >> 1;        // 0..127 : (h, p) pair
    int h  = pi >> 4;
    int pl = pi & 15;
    int d0 = (t & 1) * 8;

    // q for this (p, h) in registers (avoids 16-way LDS conflicts)
    float qr[16];
    {
        const float* qptr = g_Q + (size_t)(b * PP + p0 + pl) * 128 + h * 16;
#pragma unroll
        for (int d = 0; d < 16; d++) qr[d] = qptr[d];
    }

    float m = -1e30f, l = 0.f;
    float acc[8] = {0, 0, 0, 0, 0, 0, 0, 0};

    const float* Kb = g_K + (size_t)b * NN * 128;
    const float* Vb = g_V + (size_t)b * NN * 128;
    const float* Mb = mask + (size_t)(b * PP + p0) * NN;

    for (int base = 0; base < NN; base += CC) {
        int nv = NN - base; if (nv > CC) nv = CC;
        // stage K, V chunk (coalesced float4)
        {
            const float4* ksrc = (const float4*)(Kb + (size_t)base * 128);
            const float4* vsrc = (const float4*)(Vb + (size_t)base * 128);
            int lim = nv * 32;
            for (int i = t; i < lim; i += 256) {
                ((float4*)ke_s)[i] = ksrc[i];
                ((float4*)v_s)[i]  = vsrc[i];
            }
        }
        // stage mask chunk
        for (int i = t; i < PT * CC; i += 256) {
            int p = i >> 5, n = i & 31;
            mask_s[i] = (n < nv) ? Mb[(size_t)p * NN + base + n] : 0.f;
        }
        __syncthreads();

        // scores: each thread does 16 n's for its (h,p)
        {
            int nb = (t & 1) * 16;
#pragma unroll
            for (int i = 0; i < 16; i++) {
                int n = nb + i;
                float s;
                if (n < nv) {
                    const float* kp = ke_s + n * 128 + h * 16;
                    s = 0.f;
#pragma unroll
                    for (int d = 0; d < 16; d++) s += qr[d] * kp[d];
                    s = s * 0.25f + mask_s[pl * 32 + n];
                } else {
                    s = -1e30f;
                }
                s_s[pi * 33 + n] = s;
            }
        }
        __syncthreads();

        // online-softmax bookkeeping (even thread of each pair)
        if ((t & 1) == 0) {
            float cm = -1e30f;
#pragma unroll
            for (int n = 0; n < 32; n++) cm = fmaxf(cm, s_s[pi * 33 + n]);
            float nm = fmaxf(m, cm);
            float r = __expf(m - nm);
            float sum = 0.f;
#pragma unroll
            for (int n = 0; n < 32; n++) {
                float w = __expf(s_s[pi * 33 + n] - nm);
                s_s[pi * 33 + n] = w;
                sum += w;
            }
            l = l * r + sum;
            m = nm;
            resc[pi] = r;
        }
        __syncthreads();

        // accumulate V (both threads of pair, 8 d's each)
        {
            float r = resc[pi];
#pragma unroll
            for (int j = 0; j < 8; j++) acc[j] *= r;
            for (int n = 0; n < 32; n++) {
                float w = s_s[pi * 33 + n];
                const float* vp = v_s + n * 128 + h * 16 + d0;
#pragma unroll
                for (int j = 0; j < 8; j++) acc[j] += w * vp[j];
            }
        }
        __syncthreads();
    }

    // finalize attention output
    if ((t & 1) == 0) l_s[pi] = l;
    __syncthreads();
    {
        float inv = 1.f / l_s[pi];
#pragma unroll
        for (int j = 0; j < 8; j++)
            out_s[pl * 128 + h * 16 + d0 + j] = acc[j] * inv;
    }
    __syncthreads();

    // mh = out @ Wo + bo  (Wo through L1, coalesced)
    for (int e = t; e < PT * 128; e += 256) {
        int p = e >> 7, o = e & 127;
        float a = bo[o];
        const float* op = out_s + p * 128;
#pragma unroll 8
        for (int in = 0; in < 128; in++) a += op[in] * Wo[in * 128 + o];
        mh_s[e] = a;
    }
    __syncthreads();

    // final scoring: sc[p][n] = 10*tanh(mh.enc / sqrt(E)) + mask
    const float* Eb = enc + (size_t)b * NN * 128;
    const float inv_se = 0.08838834764831845f;
    for (int base = 0; base < NN; base += CC) {
        int nv = NN - base; if (nv > CC) nv = CC;
        for (int i = t; i < nv * 128; i += 256) {
            int n = i >> 7, c = i & 127;
            ke_s[n * 129 + c] = Eb[(size_t)(base + n) * 128 + c];
        }
        __syncthreads();
        for (int e = t; e < PT * CC; e += 256) {
            int p = e >> 5, n = e & 31;
            if (n < nv) {
                const float* ep = ke_s + n * 129;
                const float* mp = mh_s + p * 128;
                float s = 0.f;
#pragma unroll 8
                for (int k = 0; k < 128; k++) s += mp[k] * ep[k];
                s = 10.f * tanhf(s * inv_se) + Mb[(size_t)p * NN + base + n];
                sc[p * 1000 + base + n] = s;
            }
        }
        __syncthreads();
    }

    // final softmax over n per p (warp handles 2 p's) + write probs
    int warp = t >> 5, lane = t & 31;
    for (int p = warp * 2; p < warp * 2 + 2; p++) {
        const float* row = sc + p * 1000;
        float mx = -1e30f;
        for (int i = lane; i < NN; i += 32) mx = fmaxf(mx, row[i]);
#pragma unroll
        for (int off = 16; off; off >>= 1)
            mx = fmaxf(mx, __shfl_xor_sync(0xFFFFFFFFu, mx, off));
        float sum = 0.f;
        for (int i = lane; i < NN; i += 32) sum += __expf(row[i] - mx);
#pragma unroll
        for (int off = 16; off; off >>= 1)
            sum += __shfl_xor_sync(0xFFFFFFFFu, sum, off);
        float inv = 1.f / sum;
        float* op = probs + (size_t)(b * PP + p0 + p) * NN;
        for (int i = lane; i < NN; i += 32) op[i] = __expf(row[i] - mx) * inv;
    }
}

// ---------------------------------------------------------------------------
extern "C" void kernel_launch(void* const* d_in, const int* in_sizes, int n_in,
                              void* d_out, int out_size) {
    const float* enc  = (const float*)d_in[0];
    const float* last = (const float*)d_in[1];
    const float* attr = (const float*)d_in[2];
    const float* mask = (const float*)d_in[3];
    const float* Wq   = (const float*)d_in[4];
    const float* Wk   = (const float*)d_in[5];
    const float* Wv   = (const float*)d_in[6];
    const float* Wo   = (const float*)d_in[7];
    const float* bo   = (const float*)d_in[8];
    float* out = (float*)d_out;

    // 22208 floats = 88832 bytes dynamic smem for attn_kernel
    cudaFuncSetAttribute(attn_kernel,
                         cudaFuncAttributeMaxDynamicSharedMemorySize, 88832);

    kv_proj<<<8000, 256>>>(enc, Wk, Wv);
    q_proj<<<2048, 128>>>(last, attr, Wq);
    attn_kernel<<<1024, 256, 88832>>>(enc, mask, Wo, bo, out);
}

// round 3
// speedup vs baseline: 1.0009x; 1.0009x over previous
#include <cuda_runtime.h>

#define BB 64
#define PP 256
#define NN 1000
#define EE 128
#define HH 8
#define DD 16
#define HD 128
#define PT 16   // queries per attention block
#define CC 32   // n-chunk

// scratch (allowed: __device__ globals, no allocation)
__device__ float g_K[BB * NN * HD];   // 32.8 MB
__device__ float g_V[BB * NN * HD];   // 32.8 MB
__device__ float g_Q[BB * PP * HD];   //  8.4 MB

// ---------------------------------------------------------------------------
// Kernel A: K/V projection.  rows = B*N = 64000, 8 rows/block, 256 threads.
// threads 0..127 -> K (Wk), 128..255 -> V (Wv). W cached in L1, 8-row reuse.
// ---------------------------------------------------------------------------
__global__ void kv_proj(const float* __restrict__ enc,
                        const float* __restrict__ Wk,
                        const float* __restrict__ Wv) {
    __shared__ float xs[8 * 128];
    int row0 = blockIdx.x * 8;
    int t = threadIdx.x;
    const float* src = enc + (size_t)row0 * 128;
    for (int i = t; i < 1024; i += 256) xs[i] = src[i];
    __syncthreads();

    int col = t & 127;
    const float* W = (t < 128) ? Wk : Wv;
    float* out = (t < 128) ? g_K : g_V;
    float acc[8] = {0, 0, 0, 0, 0, 0, 0, 0};
#pragma unroll 4
    for (int in = 0; in < 128; in++) {
        float w = W[in * 128 + col];
#pragma unroll
        for (int r = 0; r < 8; r++) acc[r] += xs[r * 128 + in] * w;
    }
#pragma unroll
    for (int r = 0; r < 8; r++) out[(size_t)(row0 + r) * 128 + col] = acc[r];
}

// ---------------------------------------------------------------------------
// Kernel B: Q projection (concat(last, attr) @ Wq).  rows = B*P = 16384,
// 8 rows/block, 128 threads, K=129.
// ---------------------------------------------------------------------------
__global__ void q_proj(const float* __restrict__ last,
                       const float* __restrict__ attr,
                       const float* __restrict__ Wq) {
    __shared__ float xs[8 * 132];
    int row0 = blockIdx.x * 8;
    int t = threadIdx.x;  // 128
    for (int i = t; i < 1024; i += 128) {
        int r = i >> 7, c = i & 127;
        xs[r * 132 + c] = last[(size_t)(row0 + r) * 128 + c];
    }
    if (t < 8) xs[t * 132 + 128] = attr[row0 + t];
    __syncthreads();

    float acc[8] = {0, 0, 0, 0, 0, 0, 0, 0};
#pragma unroll 4
    for (int in = 0; in < 129; in++) {
        float w = Wq[in * 128 + t];
#pragma unroll
        for (int r = 0; r < 8; r++) acc[r] += xs[r * 132 + in] * w;
    }
#pragma unroll
    for (int r = 0; r < 8; r++) g_Q[(size_t)(row0 + r) * 128 + t] = acc[r];
}

// ---------------------------------------------------------------------------
// Kernel C: fused attention + Wo + tanh-clipped scoring + final softmax.
// block = (b, 16-query tile). 256 threads, 1024 blocks.
// Online (flash) softmax over n-chunks of 32.
// Thread pairing: pi = t>>1 owns (head h = pi>>4, p = pi&15); the pair splits
// the D=16 accumulator 8/8 (d0 = (t&1)*8). Even thread does softmax bookkeeping.
// ---------------------------------------------------------------------------
__global__ void attn_kernel(const float* __restrict__ enc,
                            const float* __restrict__ mask,
                            const float* __restrict__ Wo,
                            const float* __restrict__ bo,
                            float* __restrict__ probs) {
    extern __shared__ float sm[];
    // layout (floats):
    //   [0, 2048)        mh_s (phase B)
    //   [2048, 6208)     ke_s : K chunk (stride 128) / enc chunk (stride 129)
    //   [6208, 22208)    big:
    //      phase A: v_s 4096 | s_s 4224 (stride 33) | mask_s 512 | resc 128 |
    //               l_s 128 | out_s 2048
    //      phase B: sc[16*1000]
    float* mh_s  = sm;
    float* ke_s  = sm + 2048;
    float* big   = sm + 6208;
    float* v_s    = big;
    float* s_s    = big + 4096;
    float* mask_s = big + 8320;
    float* resc   = big + 8832;
    float* l_s    = big + 8960;
    float* out_s  = big + 9088;
    float* sc     = big;

    int t = threadIdx.x;
    int b = blockIdx.x >> 4;
    int p0 = (blockIdx.x & 15) * PT;

    int pi = t >> 1;        // 0..127 : (h, p) pair
    int h  = pi >> 4;
    int pl = pi & 15;
    int d0 = (t & 1) * 8;

    // q for this (p, h) in registers (avoids 16-way LDS conflicts)
    float qr[16];
    {
        const float* qptr = g_Q + (size_t)(b * PP + p0 + pl) * 128 + h * 16;
#pragma unroll
        for (int d = 0; d < 16; d++) qr[d] = qptr[d];
    }

    float m = -1e30f, l = 0.f;
    float acc[8] = {0, 0, 0, 0, 0, 0, 0, 0};

    const float* Kb = g_K + (size_t)b * NN * 128;
    const float* Vb = g_V + (size_t)b * NN * 128;
    const float* Mb = mask + (size_t)(b * PP + p0) * NN;

    for (int base = 0; base < NN; base += CC) {
        int nv = NN - base; if (nv > CC) nv = CC;
        // stage K, V chunk (coalesced float4)
        {
            const float4* ksrc = (const float4*)(Kb + (size_t)base * 128);
            const float4* vsrc = (const float4*)(Vb + (size_t)base * 128);
            int lim = nv * 32;
            for (int i = t; i < lim; i += 256) {
                ((float4*)ke_s)[i] = ksrc[i];
                ((float4*)v_s)[i]  = vsrc[i];
            }
        }
        // stage mask chunk
        for (int i = t; i < PT * CC; i += 256) {
            int p = i >> 5, n = i & 31;
            mask_s[i] = (n < nv) ? Mb[(size_t)p * NN + base + n] : 0.f;
        }
        __syncthreads();

        // scores: each thread does 16 n's for its (h,p)
        {
            int nb = (t & 1) * 16;
#pragma unroll
            for (int i = 0; i < 16; i++) {
                int n = nb + i;
                float s;
                if (n < nv) {
                    const float* kp = ke_s + n * 128 + h * 16;
                    s = 0.f;
#pragma unroll
                    for (int d = 0; d < 16; d++) s += qr[d] * kp[d];
                    s = s * 0.25f + mask_s[pl * 32 + n];
                } else {
                    s = -1e30f;
                }
                s_s[pi * 33 + n] = s;
            }
        }
        __syncthreads();

        // online-softmax bookkeeping (even thread of each pair)
        if ((t & 1) == 0) {
            float cm = -1e30f;
#pragma unroll
            for (int n = 0; n < 32; n++) cm = fmaxf(cm, s_s[pi * 33 + n]);
            float nm = fmaxf(m, cm);
            float r = __expf(m - nm);
            float sum = 0.f;
#pragma unroll
            for (int n = 0; n < 32; n++) {
                float w = __expf(s_s[pi * 33 + n] - nm);
                s_s[pi * 33 + n] = w;
                sum += w;
            }
            l = l * r + sum;
            m = nm;
            resc[pi] = r;
        }
        __syncthreads();

        // accumulate V (both threads of pair, 8 d's each)
        {
            float r = resc[pi];
#pragma unroll
            for (int j = 0; j < 8; j++) acc[j] *= r;
            for (int n = 0; n < 32; n++) {
                float w = s_s[pi * 33 + n];
                const float* vp = v_s + n * 128 + h * 16 + d0;
#pragma unroll
                for (int j = 0; j < 8; j++) acc[j] += w * vp[j];
            }
        }
        __syncthreads();
    }

    // finalize attention output
    if ((t & 1) == 0) l_s[pi] = l;
    __syncthreads();
    {
        float inv = 1.f / l_s[pi];
#pragma unroll
        for (int j = 0; j < 8; j++)
            out_s[pl * 128 + h * 16 + d0 + j] = acc[j] * inv;
    }
    __syncthreads();

    // mh = out @ Wo + bo  (Wo through L1, coalesced)
    for (int e = t; e < PT * 128; e += 256) {
        int p = e >> 7, o = e & 127;
        float a = bo[o];
        const float* op = out_s + p * 128;
#pragma unroll 8
        for (int in = 0; in < 128; in++) a += op[in] * Wo[in * 128 + o];
        mh_s[e] = a;
    }
    __syncthreads();

    // final scoring: sc[p][n] = 10*tanh(mh.enc / sqrt(E)) + mask
    const float* Eb = enc + (size_t)b * NN * 128;
    const float inv_se = 0.08838834764831845f;
    for (int base = 0; base < NN; base += CC) {
        int nv = NN - base; if (nv > CC) nv = CC;
        for (int i = t; i < nv * 128; i += 256) {
            int n = i >> 7, c = i & 127;
            ke_s[n * 129 + c] = Eb[(size_t)(base + n) * 128 + c];
        }
        __syncthreads();
        for (int e = t; e < PT * CC; e += 256) {
            int p = e >> 5, n = e & 31;
            if (n < nv) {
                const float* ep = ke_s + n * 129;
                const float* mp = mh_s + p * 128;
                float s = 0.f;
#pragma unroll 8
                for (int k = 0; k < 128; k++) s += mp[k] * ep[k];
                s = 10.f * tanhf(s * inv_se) + Mb[(size_t)p * NN + base + n];
                sc[p * 1000 + base + n] = s;
            }
        }
        __syncthreads();
    }

    // final softmax over n per p (warp handles 2 p's) + write probs
    int warp = t >> 5, lane = t & 31;
    for (int p = warp * 2; p < warp * 2 + 2; p++) {
        const float* row = sc + p * 1000;
        float mx = -1e30f;
        for (int i = lane; i < NN; i += 32) mx = fmaxf(mx, row[i]);
#pragma unroll
        for (int off = 16; off; off >>= 1)
            mx = fmaxf(mx, __shfl_xor_sync(0xFFFFFFFFu, mx, off));
        float sum = 0.f;
        for (int i = lane; i < NN; i += 32) sum += __expf(row[i] - mx);
#pragma unroll
        for (int off = 16; off; off >>= 1)
            sum += __shfl_xor_sync(0xFFFFFFFFu, sum, off);
        float inv = 1.f / sum;
        float* op = probs + (size_t)(b * PP + p0 + p) * NN;
        for (int i = lane; i < NN; i += 32) op[i] = __expf(row[i] - mx) * inv;
    }
}

// ---------------------------------------------------------------------------
extern "C" void kernel_launch(void* const* d_in, const int* in_sizes, int n_in,
                              void* d_out, int out_size) {
    const float* enc  = (const float*)d_in[0];
    const float* last = (const float*)d_in[1];
    const float* attr = (const float*)d_in[2];
    const float* mask = (const float*)d_in[3];
    const float* Wq   = (const float*)d_in[4];
    const float* Wk   = (const float*)d_in[5];
    const float* Wv   = (const float*)d_in[6];
    const float* Wo   = (const float*)d_in[7];
    const float* bo   = (const float*)d_in[8];
    float* out = (float*)d_out;

    // 22208 floats = 88832 bytes dynamic smem for attn_kernel
    cudaFuncSetAttribute(attn_kernel,
                         cudaFuncAttributeMaxDynamicSharedMemorySize, 88832);

    kv_proj<<<8000, 256>>>(enc, Wk, Wv);
    q_proj<<<2048, 128>>>(last, attr, Wq);
    attn_kernel<<<1024, 256, 88832>>>(enc, mask, Wo, bo, out);
}

// round 4
// speedup vs baseline: 1.8028x; 1.8011x over previous
#include <cuda_runtime.h>
#include <cstdint>

#define BB 64
#define PP 256
#define NN 1000
typedef unsigned long long ull;

__device__ float g_K[BB * NN * 128];
__device__ float g_V[BB * NN * 128];
__device__ float g_Q[BB * PP * 128];

// ---- f32x2 helpers ----
__device__ __forceinline__ ull ffma2(ull a, ull b, ull c) {
    ull d; asm("fma.rn.f32x2 %0,%1,%2,%3;" : "=l"(d) : "l"(a), "l"(b), "l"(c)); return d;
}
__device__ __forceinline__ ull fmul2(ull a, ull b) {
    ull d; asm("mul.rn.f32x2 %0,%1,%2;" : "=l"(d) : "l"(a), "l"(b)); return d;
}
__device__ __forceinline__ ull fadd2(ull a, ull b) {
    ull d; asm("add.rn.f32x2 %0,%1,%2;" : "=l"(d) : "l"(a), "l"(b)); return d;
}
__device__ __forceinline__ ull pack2(float lo, float hi) {
    ull d; asm("mov.b64 %0,{%1,%2};" : "=l"(d) : "f"(lo), "f"(hi)); return d;
}
__device__ __forceinline__ float hadd2(ull a) {
    float lo, hi; asm("mov.b64 {%0,%1},%2;" : "=f"(lo), "=f"(hi) : "l"(a)); return lo + hi;
}
__device__ __forceinline__ void lds2x64(const float* p, ull& a, ull& b) {
    uint32_t ad = (uint32_t)__cvta_generic_to_shared(p);
    asm("ld.shared.v2.b64 {%0,%1},[%2];" : "=l"(a), "=l"(b) : "r"(ad));
}
__device__ __forceinline__ ull lds64(const float* p) {
    uint32_t ad = (uint32_t)__cvta_generic_to_shared(p);
    ull a; asm("ld.shared.b64 %0,[%1];" : "=l"(a) : "r"(ad)); return a;
}
__device__ __forceinline__ void sts64(float* p, ull v) {
    uint32_t ad = (uint32_t)__cvta_generic_to_shared(p);
    asm volatile("st.shared.b64 [%0],%1;" :: "r"(ad), "l"(v));
}
__device__ __forceinline__ void ldg2x64(const float* p, ull& a, ull& b) {
    asm("ld.global.nc.v2.b64 {%0,%1},[%2];" : "=l"(a), "=l"(b) : "l"(p));
}

// ---------------------------------------------------------------------------
// K/V projection: 32 rows/block, 256 threads.
// thread = (mat, row-half, col-pair): 16 rows x 2 cols, f32x2 along K.
// ---------------------------------------------------------------------------
__global__ __launch_bounds__(256) void kv_proj(const float* __restrict__ enc,
                                               const float* __restrict__ Wk,
                                               const float* __restrict__ Wv) {
    __shared__ float xs[32 * 128];
    int t = threadIdx.x;
    int row0 = blockIdx.x * 32;
    const float4* src = (const float4*)(enc + (size_t)row0 * 128);
    float4* xs4 = (float4*)xs;
#pragma unroll
    for (int i = t; i < 1024; i += 256) xs4[i] = src[i];
    __syncthreads();

    int mat = t >> 7, rh = (t >> 6) & 1, cp = t & 63;
    const float* W = mat ? Wv : Wk;
    float* out = mat ? g_V : g_K;
    const float* xb = xs + rh * 2048;

    ull acc[32];
#pragma unroll
    for (int i = 0; i < 32; i++) acc[i] = 0ull;

#pragma unroll 2
    for (int k = 0; k < 128; k += 2) {
        ull w0 = pack2(W[k * 128 + cp], W[(k + 1) * 128 + cp]);
        ull w1 = pack2(W[k * 128 + cp + 64], W[(k + 1) * 128 + cp + 64]);
#pragma unroll
        for (int r = 0; r < 16; r++) {
            ull x = lds64(xb + r * 128 + k);
            acc[r]      = ffma2(x, w0, acc[r]);
            acc[16 + r] = ffma2(x, w1, acc[16 + r]);
        }
    }
#pragma unroll
    for (int r = 0; r < 16; r++) {
        size_t row = (size_t)(row0 + rh * 16 + r) * 128;
        out[row + cp]      = hadd2(acc[r]);
        out[row + cp + 64] = hadd2(acc[16 + r]);
    }
}

// ---------------------------------------------------------------------------
// Q projection (small)
// ---------------------------------------------------------------------------
__global__ void q_proj(const float* __restrict__ last,
                       const float* __restrict__ attr,
                       const float* __restrict__ Wq) {
    __shared__ float xs[8 * 132];
    int row0 = blockIdx.x * 8;
    int t = threadIdx.x;  // 128
    for (int i = t; i < 1024; i += 128) {
        int r = i >> 7, c = i & 127;
        xs[r * 132 + c] = last[(size_t)(row0 + r) * 128 + c];
    }
    if (t < 8) xs[t * 132 + 128] = attr[row0 + t];
    __syncthreads();

    float acc[8] = {0, 0, 0, 0, 0, 0, 0, 0};
#pragma unroll 4
    for (int in = 0; in < 129; in++) {
        float w = Wq[in * 128 + t];
#pragma unroll
        for (int r = 0; r < 8; r++) acc[r] += xs[r * 132 + in] * w;
    }
#pragma unroll
    for (int r = 0; r < 8; r++) g_Q[(size_t)(row0 + r) * 128 + t] = acc[r];
}

// ---------------------------------------------------------------------------
// Fused attention + Wo + tanh scoring + final softmax.
// block = (b, 16-query tile), 256 threads.
// Phase A thread map: h = t>>5 (warp=head), pl = (t>>1)&15, half = t&1
//   (n parity). All k/v LDS are warp-broadcasts in distinct bank quads.
// smem (floats): mh[0,2112) inv[2112,2128) work[2128, +16896)
//   phase A in work: k 4224 | v 4224 | mask 528 | out 2112
//   phase B in work: enc 16896
// ---------------------------------------------------------------------------
__global__ __launch_bounds__(256, 2) void attn_kernel(
        const float* __restrict__ enc, const float* __restrict__ mask,
        const float* __restrict__ Wo, const float* __restrict__ bo,
        float* __restrict__ probs) {
    extern __shared__ float sm[];
    float* mh_s  = sm;
    float* inv_s = sm + 2112;
    float* work  = sm + 2128;
    float* k_s    = work;
    float* v_s    = work + 4224;
    float* mask_s = work + 8448;
    float* out_s  = work + 8976;
    float* enc_s  = work;

    int t = threadIdx.x;
    int b = blockIdx.x >> 4;
    int p0 = (blockIdx.x & 15) * 16;

    int h = t >> 5, pl = (t >> 1) & 15, half = t & 1;

    // q in registers, packed
    ull qr[8];
    {
        const float* qp = g_Q + (size_t)(b * PP + p0 + pl) * 128 + h * 16;
#pragma unroll
        for (int j = 0; j < 4; j++) lds2x64(qp + 4 * j, qr[2 * j], qr[2 * j + 1]); // generic->global ok? no:
    }
    // (qp is global; redo with ldg)
    {
        const float* qp = g_Q + (size_t)(b * PP + p0 + pl) * 128 + h * 16;
#pragma unroll
        for (int j = 0; j < 4; j++) ldg2x64(qp + 4 * j, qr[2 * j], qr[2 * j + 1]);
    }

    float m = -1e30f, l = 0.f;
    ull acc[8];
#pragma unroll
    for (int j = 0; j < 8; j++) acc[j] = 0ull;

    const float4* Kb = (const float4*)(g_K + (size_t)b * NN * 128);
    const float4* Vb = (const float4*)(g_V + (size_t)b * NN * 128);
    const float* Mb = mask + (size_t)(b * PP + p0) * NN;

    for (int base = 0; base < NN; base += 32) {
        int nv = NN - base; if (nv > 32) nv = 32;
        // stage K,V (stride-132 rows), mask
        {
            float4* ks4 = (float4*)k_s;
            float4* vs4 = (float4*)v_s;
            int lim = nv * 32, off = base * 32;
            for (int i = t; i < lim; i += 256) {
                int n = i >> 5, c = i & 31;
                ks4[n * 33 + c] = Kb[off + i];
                vs4[n * 33 + c] = Vb[off + i];
            }
            for (int i = t; i < 512; i += 256) {
                int p = i >> 5, n = i & 31;
                mask_s[p * 33 + n] = (n < nv) ? Mb[(size_t)p * NN + base + n] : 0.f;
            }
        }
        __syncthreads();

        float s[16];
        float cmax = -1e30f;
#pragma unroll
        for (int i = 0; i < 16; i++) {
            int n = 2 * i + half;
            const float* kp = k_s + n * 132 + h * 16;
            ull k0, k1, k2, k3, k4, k5, k6, k7;
            lds2x64(kp,      k0, k1);
            lds2x64(kp + 4,  k2, k3);
            lds2x64(kp + 8,  k4, k5);
            lds2x64(kp + 12, k6, k7);
            ull d = fmul2(qr[0], k0);
            d = ffma2(qr[1], k1, d); d = ffma2(qr[2], k2, d);
            d = ffma2(qr[3], k3, d); d = ffma2(qr[4], k4, d);
            d = ffma2(qr[5], k5, d); d = ffma2(qr[6], k6, d);
            d = ffma2(qr[7], k7, d);
            float sv = hadd2(d) * 0.25f + mask_s[pl * 33 + n];
            s[i] = (n < nv) ? sv : -1e30f;
            cmax = fmaxf(cmax, s[i]);
        }
        cmax = fmaxf(cmax, __shfl_xor_sync(0xFFFFFFFFu, cmax, 1));
        float nm = fmaxf(m, cmax);
        float r = __expf(m - nm);
        m = nm;
        float lsum = 0.f;
#pragma unroll
        for (int i = 0; i < 16; i++) { s[i] = __expf(s[i] - m); lsum += s[i]; }
        l = l * r + lsum;
        ull rr = pack2(r, r);
#pragma unroll
        for (int j = 0; j < 8; j++) acc[j] = fmul2(acc[j], rr);
#pragma unroll
        for (int i = 0; i < 16; i++) {
            int n = 2 * i + half;
            const float* vp = v_s + n * 132 + h * 16;
            ull v0, v1, v2, v3, v4, v5, v6, v7;
            lds2x64(vp,      v0, v1);
            lds2x64(vp + 4,  v2, v3);
            lds2x64(vp + 8,  v4, v5);
            lds2x64(vp + 12, v6, v7);
            ull w = pack2(s[i], s[i]);
            acc[0] = ffma2(w, v0, acc[0]); acc[1] = ffma2(w, v1, acc[1]);
            acc[2] = ffma2(w, v2, acc[2]); acc[3] = ffma2(w, v3, acc[3]);
            acc[4] = ffma2(w, v4, acc[4]); acc[5] = ffma2(w, v5, acc[5]);
            acc[6] = ffma2(w, v6, acc[6]); acc[7] = ffma2(w, v7, acc[7]);
        }
        __syncthreads();
    }

    // merge n-parity partners
    float lt = l + __shfl_xor_sync(0xFFFFFFFFu, l, 1);
    float inv = 1.f / lt;
    ull iv = pack2(inv, inv);
#pragma unroll
    for (int j = 0; j < 8; j++) {
        ull o = __shfl_xor_sync(0xFFFFFFFFu, acc[j], 1);
        acc[j] = fmul2(fadd2(acc[j], o), iv);
    }
    {
        float* op = out_s + pl * 132 + h * 16 + half * 8;
#pragma unroll
        for (int jj = 0; jj < 4; jj++) sts64(op + 2 * jj, acc[half * 4 + jj]);
    }
    __syncthreads();

    // Wo GEMM: thread = (p = t>>4, 8 e's at eg)
    {
        int p = t >> 4;
        int eg = (t & 15) * 8;
        ull a0, a1, a2, a3;
        ldg2x64(bo + eg, a0, a1);
        ldg2x64(bo + eg + 4, a2, a3);
        const float* op = out_s + p * 132;
#pragma unroll 4
        for (int in = 0; in < 128; in++) {
            float x = op[in];
            ull xx = pack2(x, x);
            ull w0, w1, w2, w3;
            ldg2x64(Wo + in * 128 + eg, w0, w1);
            ldg2x64(Wo + in * 128 + eg + 4, w2, w3);
            a0 = ffma2(xx, w0, a0); a1 = ffma2(xx, w1, a1);
            a2 = ffma2(xx, w2, a2); a3 = ffma2(xx, w3, a3);
        }
        float* mp = mh_s + p * 132 + eg;
        sts64(mp, a0); sts64(mp + 2, a1); sts64(mp + 4, a2); sts64(mp + 6, a3);
    }
    __syncthreads();

    // Phase B: final scoring. thread = (pg = t>>5 -> 2 p's, ng = t&31 -> 4 n's)
    int pg = t >> 5, ng = t & 31;
    float rs0 = 0.f, rs1 = 0.f;
    const float4* Eb4 = (const float4*)(enc + (size_t)b * NN * 128);
    float* pout = probs + (size_t)(b * PP + p0) * NN;
    const float inv_se = 0.08838834764831845f;
    const float* mrow0 = mh_s + (2 * pg) * 132;
    const float* mrow1 = mrow0 + 132;

    for (int base = 0; base < NN; base += 128) {
        int nv = NN - base; if (nv > 128) nv = 128;
        {
            float4* es4 = (float4*)enc_s;
            int lim = nv * 32, off = base * 32;
            for (int i = t; i < lim; i += 256) {
                int n = i >> 5, c = i & 31;
                es4[n * 33 + c] = Eb4[off + i];
            }
        }
        __syncthreads();

        ull a[2][4];
#pragma unroll
        for (int pp = 0; pp < 2; pp++)
#pragma unroll
            for (int j = 0; j < 4; j++) a[pp][j] = 0ull;

#pragma unroll 4
        for (int k = 0; k < 128; k += 4) {
            ull m00, m01, m10, m11;
            lds2x64(mrow0 + k, m00, m01);
            lds2x64(mrow1 + k, m10, m11);
#pragma unroll
            for (int j = 0; j < 4; j++) {
                const float* ep = enc_s + (ng + 32 * j) * 132 + k;
                ull e0, e1; lds2x64(ep, e0, e1);
                a[0][j] = ffma2(m00, e0, a[0][j]);
                a[0][j] = ffma2(m01, e1, a[0][j]);
                a[1][j] = ffma2(m10, e0, a[1][j]);
                a[1][j] = ffma2(m11, e1, a[1][j]);
            }
        }
#pragma unroll
        for (int j = 0; j < 4; j++) {
            int n = ng + 32 * j;
            if (n < nv) {
#pragma unroll
                for (int pp = 0; pp < 2; pp++) {
                    int p = 2 * pg + pp;
                    float sd = hadd2(a[pp][j]);
                    float lg = 10.f * tanhf(sd * inv_se)
                             + Mb[(size_t)p * NN + base + n];
                    float w = __expf(lg - 10.f);
                    if (pp) rs1 += w; else rs0 += w;
                    pout[(size_t)p * NN + base + n] = w;
                }
            }
        }
        __syncthreads();
    }

    // row sums -> inverse, then normalize in-place
#pragma unroll
    for (int off = 16; off; off >>= 1) {
        rs0 += __shfl_xor_sync(0xFFFFFFFFu, rs0, off);
        rs1 += __shfl_xor_sync(0xFFFFFFFFu, rs1, off);
    }
    if (ng == 0) {
        inv_s[2 * pg]     = 1.f / rs0;
        inv_s[2 * pg + 1] = 1.f / rs1;
    }
    __syncthreads();
#pragma unroll
    for (int p = 0; p < 16; p++) {
        float ivp = inv_s[p];
        for (int i = t; i < NN; i += 256)
            pout[(size_t)p * NN + i] *= ivp;
    }
}

// ---------------------------------------------------------------------------
extern "C" void kernel_launch(void* const* d_in, const int* in_sizes, int n_in,
                              void* d_out, int out_size) {
    const float* enc  = (const float*)d_in[0];
    const float* last = (const float*)d_in[1];
    const float* attr = (const float*)d_in[2];
    const float* mask = (const float*)d_in[3];
    const float* Wq   = (const float*)d_in[4];
    const float* Wk   = (const float*)d_in[5];
    const float* Wv   = (const float*)d_in[6];
    const float* Wo   = (const float*)d_in[7];
    const float* bo   = (const float*)d_in[8];
    float* out = (float*)d_out;

    cudaFuncSetAttribute(attn_kernel,
                         cudaFuncAttributeMaxDynamicSharedMemorySize, 76096);

    kv_proj<<<2000, 256>>>(enc, Wk, Wv);
    q_proj<<<2048, 128>>>(last, attr, Wq);
    attn_kernel<<<1024, 256, 76096>>>(enc, mask, Wo, bo, out);
}

// round 5
// speedup vs baseline: 1.9704x; 1.0930x over previous
#include <cuda_runtime.h>
#include <cstdint>

#define BB 64
#define PP 256
#define NN 1000
typedef unsigned long long ull;

__device__ float g_K[BB * NN * 128];
__device__ float g_V[BB * NN * 128];
__device__ float g_Q[BB * PP * 128];
__device__ float g_Wt[2 * 128 * 128];   // [mat][col][k]

// ---- f32x2 / memory helpers ----
__device__ __forceinline__ ull ffma2(ull a, ull b, ull c) {
    ull d; asm("fma.rn.f32x2 %0,%1,%2,%3;" : "=l"(d) : "l"(a), "l"(b), "l"(c)); return d;
}
__device__ __forceinline__ ull fmul2(ull a, ull b) {
    ull d; asm("mul.rn.f32x2 %0,%1,%2;" : "=l"(d) : "l"(a), "l"(b)); return d;
}
__device__ __forceinline__ ull fadd2(ull a, ull b) {
    ull d; asm("add.rn.f32x2 %0,%1,%2;" : "=l"(d) : "l"(a), "l"(b)); return d;
}
__device__ __forceinline__ ull pack2(float lo, float hi) {
    ull d; asm("mov.b64 %0,{%1,%2};" : "=l"(d) : "f"(lo), "f"(hi)); return d;
}
__device__ __forceinline__ float hadd2(ull a) {
    float lo, hi; asm("mov.b64 {%0,%1},%2;" : "=f"(lo), "=f"(hi) : "l"(a)); return lo + hi;
}
__device__ __forceinline__ void lds2x64(const float* p, ull& a, ull& b) {
    uint32_t ad = (uint32_t)__cvta_generic_to_shared(p);
    asm("ld.shared.v2.b64 {%0,%1},[%2];" : "=l"(a), "=l"(b) : "r"(ad));
}
__device__ __forceinline__ ull lds64(const float* p) {
    uint32_t ad = (uint32_t)__cvta_generic_to_shared(p);
    ull a; asm("ld.shared.b64 %0,[%1];" : "=l"(a) : "r"(ad)); return a;
}
__device__ __forceinline__ void sts64(float* p, ull v) {
    uint32_t ad = (uint32_t)__cvta_generic_to_shared(p);
    asm volatile("st.shared.b64 [%0],%1;" :: "r"(ad), "l"(v));
}
__device__ __forceinline__ void ldg2x64(const float* p, ull& a, ull& b) {
    asm("ld.global.nc.v2.b64 {%0,%1},[%2];" : "=l"(a), "=l"(b) : "l"(p));
}
__device__ __forceinline__ void cp16(float* dst, const float* src) {
    uint32_t d = (uint32_t)__cvta_generic_to_shared(dst);
    asm volatile("cp.async.cg.shared.global [%0],[%1],16;" :: "r"(d), "l"(src));
}
__device__ __forceinline__ void cp_commit() {
    asm volatile("cp.async.commit_group;");
}
template <int N> __device__ __forceinline__ void cp_wait() {
    asm volatile("cp.async.wait_group %0;" :: "n"(N));
}

// ---------------------------------------------------------------------------
// W transpose: g_Wt[m][c][k] = W_m[k][c]
// ---------------------------------------------------------------------------
__global__ void transpose_w(const float* __restrict__ Wk,
                            const float* __restrict__ Wv) {
    int idx = blockIdx.x * 256 + threadIdx.x;   // 32768 total
    int m = idx >> 14, rem = idx & 16383;
    int c = rem >> 7, k = rem & 127;
    const float* W = m ? Wv : Wk;
    g_Wt[idx] = W[k * 128 + c];
}

// ---------------------------------------------------------------------------
// K/V projection: 32 rows/block, 256 threads, transposed-W loads.
// thread = (mat, row-half, col-pair): 16 rows x 2 cols, f32x2 along K.
// ---------------------------------------------------------------------------
__global__ __launch_bounds__(256) void kv_proj(const float* __restrict__ enc) {
    __shared__ float xs[32 * 128];
    int t = threadIdx.x;
    int row0 = blockIdx.x * 32;
    const float4* src = (const float4*)(enc + (size_t)row0 * 128);
    float4* xs4 = (float4*)xs;
#pragma unroll
    for (int i = t; i < 1024; i += 256) xs4[i] = src[i];
    __syncthreads();

    int mat = t >> 7, rh = (t >> 6) & 1, cp = t & 63;
    const float* Wt = g_Wt + mat * 16384;
    float* out = mat ? g_V : g_K;
    const float* xb = xs + rh * 2048;

    ull acc[32];
#pragma unroll
    for (int i = 0; i < 32; i++) acc[i] = 0ull;

#pragma unroll 2
    for (int k = 0; k < 128; k += 4) {
        ull wa0, wb0, wa1, wb1;
        ldg2x64(Wt + cp * 128 + k, wa0, wb0);
        ldg2x64(Wt + (cp + 64) * 128 + k, wa1, wb1);
#pragma unroll
        for (int r = 0; r < 16; r++) {
            ull x0, x1;
            lds2x64(xb + r * 128 + k, x0, x1);
            acc[r]      = ffma2(x0, wa0, acc[r]);
            acc[r]      = ffma2(x1, wb0, acc[r]);
            acc[16 + r] = ffma2(x0, wa1, acc[16 + r]);
            acc[16 + r] = ffma2(x1, wb1, acc[16 + r]);
        }
    }
#pragma unroll
    for (int r = 0; r < 16; r++) {
        size_t row = (size_t)(row0 + rh * 16 + r) * 128;
        out[row + cp]      = hadd2(acc[r]);
        out[row + cp + 64] = hadd2(acc[16 + r]);
    }
}

// ---------------------------------------------------------------------------
// Q projection: 16 rows/block, 256 threads.
// ---------------------------------------------------------------------------
__global__ __launch_bounds__(256) void q_proj(const float* __restrict__ last,
                                              const float* __restrict__ attr,
                                              const float* __restrict__ Wq) {
    __shared__ float xs[16 * 132];
    int row0 = blockIdx.x * 16;
    int t = threadIdx.x;
#pragma unroll
    for (int i = t; i < 2048; i += 256) {
        int r = i >> 7, c = i & 127;
        xs[r * 132 + c] = last[(size_t)(row0 + r) * 128 + c];
    }
    if (t < 16) xs[t * 132 + 128] = attr[row0 + t];
    __syncthreads();

    int rh = t >> 7, col = t & 127;
    const float* xr = xs + rh * 8 * 132;
    float acc[8] = {0, 0, 0, 0, 0, 0, 0, 0};
#pragma unroll 4
    for (int in = 0; in < 129; in++) {
        float w = Wq[in * 128 + col];
#pragma unroll
        for (int r = 0; r < 8; r++) acc[r] += xr[r * 132 + in] * w;
    }
#pragma unroll
    for (int r = 0; r < 8; r++)
        g_Q[(size_t)(row0 + rh * 8 + r) * 128 + col] = acc[r];
}

// ---------------------------------------------------------------------------
// Fused attention + Wo + tanh scoring + final softmax, cp.async pipelined.
// block = (b, 16-query tile), 256 threads.
// smem (floats): mh 2112 | inv 16 | out 2112 | work 18048  = 22288 (89152 B)
//   phase A work: k0 4224 | k1 4224 | v0 4224 | v1 4224 | m0 576 | m1 576
//   phase B work: enc0 8448 | enc1 8448
// ---------------------------------------------------------------------------
__global__ __launch_bounds__(256, 2) void attn_kernel(
        const float* __restrict__ enc, const float* __restrict__ mask,
        const float* __restrict__ Wo, const float* __restrict__ bo,
        float* __restrict__ probs) {
    extern __shared__ float sm[];
    float* mh_s  = sm;
    float* inv_s = sm + 2112;
    float* out_s = sm + 2128;
    float* work  = sm + 4240;

    int t = threadIdx.x;
    int b = blockIdx.x >> 4;
    int p0 = (blockIdx.x & 15) * 16;

    int h = t >> 5, pl = (t >> 1) & 15, half = t & 1;

    const float* Kb = g_K + (size_t)b * NN * 128;
    const float* Vb = g_V + (size_t)b * NN * 128;
    const float* Mb = mask + (size_t)(b * PP + p0) * NN;

    // stage helpers -------------------------------------------------------
    auto stageA = [&](int chunk) {
        int buf = chunk & 1;
        int base = chunk * 32;
        int nv = NN - base; if (nv > 32) nv = 32;
        float* kd = work + buf * 4224;
        float* vd = work + 8448 + buf * 4224;
        float* md = work + 16896 + buf * 576;
#pragma unroll
        for (int j = 0; j < 4; j++) {
            int i = t + j * 256;
            int n = i >> 5, c4 = i & 31;
            if (n < nv) {
                cp16(kd + n * 132 + c4 * 4, Kb + (size_t)(base + n) * 128 + c4 * 4);
                cp16(vd + n * 132 + c4 * 4, Vb + (size_t)(base + n) * 128 + c4 * 4);
            }
        }
        if (t < 128) {
            int p = t >> 3, s2 = t & 7;
            if (s2 * 4 < nv)
                cp16(md + p * 36 + s2 * 4, Mb + (size_t)p * NN + base + s2 * 4);
        }
    };
    auto stageB = [&](int chunk) {
        int buf = chunk & 1;
        int base = chunk * 64;
        int nv = NN - base; if (nv > 64) nv = 64;
        float* ed = work + buf * 8448;
        const float* Eb = enc + (size_t)b * NN * 128;
#pragma unroll
        for (int j = 0; j < 8; j++) {
            int i = t + j * 256;
            int n = i >> 5, c4 = i & 31;
            if (n < nv)
                cp16(ed + n * 132 + c4 * 4, Eb + (size_t)(base + n) * 128 + c4 * 4);
        }
    };

    // q in registers ------------------------------------------------------
    ull qr[8];
    {
        const float* qp = g_Q + (size_t)(b * PP + p0 + pl) * 128 + h * 16;
#pragma unroll
        for (int j = 0; j < 4; j++) ldg2x64(qp + 4 * j, qr[2 * j], qr[2 * j + 1]);
    }

    float m = -1e30f, l = 0.f;
    ull acc[8];
#pragma unroll
    for (int j = 0; j < 8; j++) acc[j] = 0ull;

    stageA(0); cp_commit();
    stageA(1); cp_commit();

    // ---- phase A: flash attention over 32 chunks of 32 keys -------------
    for (int c = 0; c < 32; c++) {
        if (c == 31) cp_wait<0>(); else cp_wait<1>();
        __syncthreads();

        int buf = c & 1;
        int base = c * 32;
        int nv = NN - base; if (nv > 32) nv = 32;
        const float* k_s    = work + buf * 4224;
        const float* v_s    = work + 8448 + buf * 4224;
        const float* mask_s = work + 16896 + buf * 576;

        float s[16];
        float cmax = -1e30f;
#pragma unroll
        for (int i = 0; i < 16; i++) {
            int n = 2 * i + half;
            const float* kp = k_s + n * 132 + h * 16;
            ull k0, k1, k2, k3, k4, k5, k6, k7;
            lds2x64(kp,      k0, k1);
            lds2x64(kp + 4,  k2, k3);
            lds2x64(kp + 8,  k4, k5);
            lds2x64(kp + 12, k6, k7);
            ull d = fmul2(qr[0], k0);
            d = ffma2(qr[1], k1, d); d = ffma2(qr[2], k2, d);
            d = ffma2(qr[3], k3, d); d = ffma2(qr[4], k4, d);
            d = ffma2(qr[5], k5, d); d = ffma2(qr[6], k6, d);
            d = ffma2(qr[7], k7, d);
            float sv = hadd2(d) * 0.25f + mask_s[pl * 36 + n];
            s[i] = (n < nv) ? sv : -1e30f;
            cmax = fmaxf(cmax, s[i]);
        }
        cmax = fmaxf(cmax, __shfl_xor_sync(0xFFFFFFFFu, cmax, 1));
        float nm = fmaxf(m, cmax);
        float r = __expf(m - nm);
        m = nm;
        float lsum = 0.f;
#pragma unroll
        for (int i = 0; i < 16; i++) { s[i] = __expf(s[i] - m); lsum += s[i]; }
        l = l * r + lsum;
        ull rr = pack2(r, r);
#pragma unroll
        for (int j = 0; j < 8; j++) acc[j] = fmul2(acc[j], rr);
#pragma unroll
        for (int i = 0; i < 16; i++) {
            int n = 2 * i + half;
            const float* vp = v_s + n * 132 + h * 16;
            ull v0, v1, v2, v3, v4, v5, v6, v7;
            lds2x64(vp,      v0, v1);
            lds2x64(vp + 4,  v2, v3);
            lds2x64(vp + 8,  v4, v5);
            lds2x64(vp + 12, v6, v7);
            ull w = pack2(s[i], s[i]);
            acc[0] = ffma2(w, v0, acc[0]); acc[1] = ffma2(w, v1, acc[1]);
            acc[2] = ffma2(w, v2, acc[2]); acc[3] = ffma2(w, v3, acc[3]);
            acc[4] = ffma2(w, v4, acc[4]); acc[5] = ffma2(w, v5, acc[5]);
            acc[6] = ffma2(w, v6, acc[6]); acc[7] = ffma2(w, v7, acc[7]);
        }
        __syncthreads();
        if (c + 2 < 32) { stageA(c + 2); cp_commit(); }
    }

    // merge n-parity partners, write out_s
    float lt = l + __shfl_xor_sync(0xFFFFFFFFu, l, 1);
    float inv = 1.f / lt;
    ull iv = pack2(inv, inv);
#pragma unroll
    for (int j = 0; j < 8; j++) {
        ull o = __shfl_xor_sync(0xFFFFFFFFu, acc[j], 1);
        acc[j] = fmul2(fadd2(acc[j], o), iv);
    }
    {
        float* op = out_s + pl * 132 + h * 16 + half * 8;
#pragma unroll
        for (int jj = 0; jj < 4; jj++) sts64(op + 2 * jj, acc[half * 4 + jj]);
    }
    __syncthreads();

    // prefetch first two enc chunks; Wo GEMM overlaps with the copies
    stageB(0); cp_commit();
    stageB(1); cp_commit();

    {
        int p = t >> 4;
        int eg = (t & 15) * 8;
        ull a0, a1, a2, a3;
        ldg2x64(bo + eg, a0, a1);
        ldg2x64(bo + eg + 4, a2, a3);
        const float* op = out_s + p * 132;
#pragma unroll 4
        for (int in = 0; in < 128; in++) {
            float x = op[in];
            ull xx = pack2(x, x);
            ull w0, w1, w2, w3;
            ldg2x64(Wo + in * 128 + eg, w0, w1);
            ldg2x64(Wo + in * 128 + eg + 4, w2, w3);
            a0 = ffma2(xx, w0, a0); a1 = ffma2(xx, w1, a1);
            a2 = ffma2(xx, w2, a2); a3 = ffma2(xx, w3, a3);
        }
        float* mp = mh_s + p * 132 + eg;
        sts64(mp, a0); sts64(mp + 2, a1); sts64(mp + 4, a2); sts64(mp + 6, a3);
    }

    // ---- phase B: tanh-clipped scoring over 16 chunks of 64 nodes -------
    int pg = t >> 5, ng = t & 31;
    float rs0 = 0.f, rs1 = 0.f;
    float* pout = probs + (size_t)(b * PP + p0) * NN;
    const float inv_se = 0.08838834764831845f;
    const float* mrow0 = mh_s + (2 * pg) * 132;
    const float* mrow1 = mrow0 + 132;

    for (int c = 0; c < 16; c++) {
        if (c == 15) cp_wait<0>(); else cp_wait<1>();
        __syncthreads();   // also publishes mh_s on c==0

        int buf = c & 1;
        int base = c * 64;
        int nv = NN - base; if (nv > 64) nv = 64;
        const float* e_s = work + buf * 8448;

        ull a[2][2];
#pragma unroll
        for (int pp = 0; pp < 2; pp++)
#pragma unroll
            for (int j = 0; j < 2; j++) a[pp][j] = 0ull;

#pragma unroll 4
        for (int k = 0; k < 128; k += 4) {
            ull m00, m01, m10, m11;
            lds2x64(mrow0 + k, m00, m01);
            lds2x64(mrow1 + k, m10, m11);
#pragma unroll
            for (int j = 0; j < 2; j++) {
                const float* ep = e_s + (ng + 32 * j) * 132 + k;
                ull e0, e1; lds2x64(ep, e0, e1);
                a[0][j] = ffma2(m00, e0, a[0][j]);
                a[0][j] = ffma2(m01, e1, a[0][j]);
                a[1][j] = ffma2(m10, e0, a[1][j]);
                a[1][j] = ffma2(m11, e1, a[1][j]);
            }
        }
#pragma unroll
        for (int j = 0; j < 2; j++) {
            int n = ng + 32 * j;
            if (n < nv) {
#pragma unroll
                for (int pp = 0; pp < 2; pp++) {
                    int p = 2 * pg + pp;
                    float sd = hadd2(a[pp][j]);
                    float x = sd * inv_se;
                    x = fminf(fmaxf(x, -30.f), 30.f);
                    float ex = __expf(-2.f * x);
                    float th = __fdividef(1.f - ex, 1.f + ex);
                    float lg = 10.f * th + Mb[(size_t)p * NN + base + n];
                    float w = __expf(lg - 10.f);
                    if (pp) rs1 += w; else rs0 += w;
                    pout[(size_t)p * NN + base + n] = w;
                }
            }
        }
        __syncthreads();
        if (c + 2 < 16) { stageB(c + 2); cp_commit(); }
    }

    // row sums -> inverse, then normalize in-place
#pragma unroll
    for (int off = 16; off; off >>= 1) {
        rs0 += __shfl_xor_sync(0xFFFFFFFFu, rs0, off);
        rs1 += __shfl_xor_sync(0xFFFFFFFFu, rs1, off);
    }
    if (ng == 0) {
        inv_s[2 * pg]     = 1.f / rs0;
        inv_s[2 * pg + 1] = 1.f / rs1;
    }
    __syncthreads();
#pragma unroll
    for (int p = 0; p < 16; p++) {
        float ivp = inv_s[p];
        for (int i = t; i < NN; i += 256)
            pout[(size_t)p * NN + i] *= ivp;
    }
}

// ---------------------------------------------------------------------------
extern "C" void kernel_launch(void* const* d_in, const int* in_sizes, int n_in,
                              void* d_out, int out_size) {
    const float* enc  = (const float*)d_in[0];
    const float* last = (const float*)d_in[1];
    const float* attr = (const float*)d_in[2];
    const float* mask = (const float*)d_in[3];
    const float* Wq   = (const float*)d_in[4];
    const float* Wk   = (const float*)d_in[5];
    const float* Wv   = (const float*)d_in[6];
    const float* Wo   = (const float*)d_in[7];
    const float* bo   = (const float*)d_in[8];
    float* out = (float*)d_out;

    cudaFuncSetAttribute(attn_kernel,
                         cudaFuncAttributeMaxDynamicSharedMemorySize, 89152);

    transpose_w<<<128, 256>>>(Wk, Wv);
    kv_proj<<<2000, 256>>>(enc);
    q_proj<<<1024, 256>>>(last, attr, Wq);
    attn_kernel<<<1024, 256, 89152>>>(enc, mask, Wo, bo, out);
}